// round 7
// baseline (speedup 1.0000x reference)
#include <cuda_runtime.h>
#include <cuda_bf16.h>
#include <mma.h>
#include <math.h>
#include <stdint.h>

using namespace nvcuda;

#define N_NODES 50000
#define N_PAD   50048
#define E_EDGES 800000
#define ET (E_EDGES + N_NODES)   // with self loops
#define F_IN 256
#define C1 256                   // HEADS*HID
#define HEADS 4
#define HID 64
#define CLS 8
#define NEG 0.2f
#define NPART ((N_NODES + 1023) / 1024)   // 49

// dual-path GEMM1 split: FFMA2 handles rows [0, 128*FF_TILES), WMMA the rest
#define FF_TILES   210
#define WMMA_TILES 181            // ceil((50000 - 210*128)/128)

// ------------------- scratch (device globals; no allocation) -------------------
__device__ float g_h1[(size_t)N_PAD * C1];       // x @ W1
__device__ float g_h2[(size_t)N_NODES * CLS];    // (agg1 out) @ W2
__device__ float g_as1[N_NODES * HEADS];
__device__ float g_ad1[N_NODES * HEADS];
__device__ float g_as2[N_NODES];
__device__ float g_ad2[N_NODES];
__device__ float4 g_ee[ET];                      // per-edge staging; reused by layer2
__device__ int   g_deg[N_NODES];
__device__ int   g_cnt[N_NODES];
__device__ int   g_rowptr[N_NODES + 1];
__device__ int   g_part[NPART];
__device__ int   g_csrc[ET];

__device__ __forceinline__ float lrelu(float x) { return x > 0.f ? x : NEG * x; }

__device__ __forceinline__ unsigned long long dup_f32(float v) {
    unsigned long long r;
    unsigned int u = __float_as_uint(v);
    asm("mov.b64 %0, {%1, %1};" : "=l"(r) : "r"(u));
    return r;
}

// ------------------- CSR build -------------------
__global__ void zero_counts_kernel() {
    int i = blockIdx.x * blockDim.x + threadIdx.x;
    if (i < N_NODES) { g_deg[i] = 0; g_cnt[i] = 0; }
}

__global__ void hist_kernel(const int* __restrict__ ei) {
    int e = blockIdx.x * blockDim.x + threadIdx.x;
    if (e >= ET) return;
    int dst = (e < E_EDGES) ? ei[E_EDGES + e] : (e - E_EDGES);
    atomicAdd(&g_deg[dst], 1);
}

__global__ void scan_a_kernel() {
    __shared__ int warpsums[32];
    int t = threadIdx.x;
    int idx = blockIdx.x * 1024 + t;
    int v = (idx < N_NODES) ? g_deg[idx] : 0;
    int x = v;
    #pragma unroll
    for (int o = 1; o < 32; o <<= 1) {
        int y = __shfl_up_sync(0xffffffffu, x, o);
        if ((t & 31) >= o) x += y;
    }
    if ((t & 31) == 31) warpsums[t >> 5] = x;
    __syncthreads();
    if (t < 32) {
        int y = warpsums[t];
        #pragma unroll
        for (int o = 1; o < 32; o <<= 1) {
            int z = __shfl_up_sync(0xffffffffu, y, o);
            if (t >= o) y += z;
        }
        warpsums[t] = y;
    }
    __syncthreads();
    int incl = x + ((t >= 32) ? warpsums[(t >> 5) - 1] : 0);
    if (idx < N_NODES) g_rowptr[idx] = incl - v;
    if (t == 1023) g_part[blockIdx.x] = incl;
}

__global__ void scan_b_kernel() {
    if (threadIdx.x == 0) {
        int run = 0;
        for (int b = 0; b < NPART; b++) {
            int v = g_part[b];
            g_part[b] = run;
            run += v;
        }
        g_rowptr[N_NODES] = run;
    }
}

__global__ void scan_c_kernel() {
    int idx = blockIdx.x * 1024 + threadIdx.x;
    if (idx < N_NODES) g_rowptr[idx] += g_part[blockIdx.x];
}

__global__ void scatter_kernel(const int* __restrict__ ei) {
    int e = blockIdx.x * blockDim.x + threadIdx.x;
    if (e >= ET) return;
    int src, dst;
    if (e < E_EDGES) { src = ei[e]; dst = ei[E_EDGES + e]; }
    else             { src = e - E_EDGES; dst = src; }
    int pos = g_rowptr[dst] + atomicAdd(&g_cnt[dst], 1);
    g_csrc[pos] = src;
}

// ------------------- GEMM1 part A: rows [0, FF_TILES*128) via fma.rn.f32x2 ----------
#define BM 128
#define BN 128
#define BK 32

__global__ __launch_bounds__(256, 2) void gemm1_kernel(const float* __restrict__ X,
                                                        const float* __restrict__ W) {
    __shared__ float As[BK][BM + 4];
    __shared__ float Bs[BK][BN];

    int bm = blockIdx.x * BM;
    int bn = blockIdx.y * BN;
    int tid = threadIdx.x;
    int tx = tid & 15;
    int ty = tid >> 4;

    unsigned long long acc[8][4];
    #pragma unroll
    for (int i = 0; i < 8; i++)
        #pragma unroll
        for (int j = 0; j < 4; j++) acc[i][j] = 0ULL;

    for (int k0 = 0; k0 < F_IN; k0 += BK) {
        #pragma unroll
        for (int it = 0; it < 4; it++) {
            int idx = tid + it * 256;
            int m  = idx >> 3, kq = idx & 7;
            int gm = bm + m;
            float4 v = make_float4(0.f, 0.f, 0.f, 0.f);
            if (gm < N_NODES) v = *(const float4*)&X[(size_t)gm * F_IN + k0 + kq * 4];
            As[kq * 4 + 0][m] = v.x;
            As[kq * 4 + 1][m] = v.y;
            As[kq * 4 + 2][m] = v.z;
            As[kq * 4 + 3][m] = v.w;
        }
        #pragma unroll
        for (int it = 0; it < 4; it++) {
            int idx = tid + it * 256;
            int k  = idx >> 5, nq = idx & 31;
            float4 v = *(const float4*)&W[(size_t)(k0 + k) * C1 + bn + nq * 4];
            *(float4*)&Bs[k][nq * 4] = v;
        }
        __syncthreads();

        #pragma unroll 4
        for (int k = 0; k < BK; k++) {
            float4 a0 = *(const float4*)&As[k][ty * 8 + 0];
            float4 a1 = *(const float4*)&As[k][ty * 8 + 4];
            unsigned long long a[8];
            a[0] = dup_f32(a0.x); a[1] = dup_f32(a0.y);
            a[2] = dup_f32(a0.z); a[3] = dup_f32(a0.w);
            a[4] = dup_f32(a1.x); a[5] = dup_f32(a1.y);
            a[6] = dup_f32(a1.z); a[7] = dup_f32(a1.w);
            const unsigned long long* brow = (const unsigned long long*)&Bs[k][0];
            unsigned long long b[4];
            #pragma unroll
            for (int j = 0; j < 4; j++) b[j] = brow[tx + 16 * j];
            #pragma unroll
            for (int i = 0; i < 8; i++)
                #pragma unroll
                for (int j = 0; j < 4; j++)
                    asm("fma.rn.f32x2 %0, %1, %2, %3;"
                        : "=l"(acc[i][j]) : "l"(a[i]), "l"(b[j]), "l"(acc[i][j]));
        }
        __syncthreads();
    }

    #pragma unroll
    for (int i = 0; i < 8; i++) {
        int gm = bm + ty * 8 + i;
        float* orow = &g_h1[(size_t)gm * C1 + bn];
        #pragma unroll
        for (int j = 0; j < 4; j++) {
            int p = tx + 16 * j;
            *(unsigned long long*)&orow[2 * p] = acc[i][j];
        }
    }
}

// ------------------- GEMM1 part B: rows [FF_TILES*128, 50048) via WMMA bf16 split ---
__global__ __launch_bounds__(256) void gemm1_wmma_kernel(const float* __restrict__ X,
                                                          const float* __restrict__ W) {
    __shared__ __nv_bfloat16 As[128][40];
    __shared__ __nv_bfloat16 Bs[32][136];

    int bm = (blockIdx.x + FF_TILES) * 128;
    int bn = blockIdx.y * 128;
    int tid = threadIdx.x;
    int wid = tid >> 5;
    int wm = wid & 3;
    int wn = wid >> 2;

    wmma::fragment<wmma::accumulator, 16, 16, 16, float> acc[2][4];
    #pragma unroll
    for (int i = 0; i < 2; i++)
        #pragma unroll
        for (int j = 0; j < 4; j++) wmma::fill_fragment(acc[i][j], 0.f);

    for (int k0 = 0; k0 < 768; k0 += 32) {
        int seg = k0 >> 8;            // 0: hi*hi, 1: hi*lo, 2: lo*hi
        bool aLo = (seg == 2);
        bool bLo = (seg == 1);
        int ksrc = k0 & 255;

        #pragma unroll
        for (int it = 0; it < 16; it++) {
            int idx = tid + it * 256;
            int m = idx >> 5, kk = idx & 31;
            int gm = bm + m;
            float v = (gm < N_NODES) ? X[(size_t)gm * F_IN + ksrc + kk] : 0.f;
            __nv_bfloat16 h = __float2bfloat16_rn(v);
            if (aLo) h = __float2bfloat16_rn(v - __bfloat162float(h));
            As[m][kk] = h;
        }
        #pragma unroll
        for (int it = 0; it < 16; it++) {
            int idx = tid + it * 256;
            int kk = idx >> 7, n = idx & 127;
            float v = W[(size_t)(ksrc + kk) * C1 + bn + n];
            __nv_bfloat16 h = __float2bfloat16_rn(v);
            if (bLo) h = __float2bfloat16_rn(v - __bfloat162float(h));
            Bs[kk][n] = h;
        }
        __syncthreads();

        #pragma unroll
        for (int ks = 0; ks < 2; ks++) {
            wmma::fragment<wmma::matrix_a, 16, 16, 16, __nv_bfloat16, wmma::row_major> af[2];
            wmma::fragment<wmma::matrix_b, 16, 16, 16, __nv_bfloat16, wmma::row_major> bf[4];
            #pragma unroll
            for (int i = 0; i < 2; i++)
                wmma::load_matrix_sync(af[i], &As[wm * 32 + i * 16][ks * 16], 40);
            #pragma unroll
            for (int j = 0; j < 4; j++)
                wmma::load_matrix_sync(bf[j], &Bs[ks * 16][wn * 64 + j * 16], 136);
            #pragma unroll
            for (int i = 0; i < 2; i++)
                #pragma unroll
                for (int j = 0; j < 4; j++)
                    wmma::mma_sync(acc[i][j], af[i], bf[j], acc[i][j]);
        }
        __syncthreads();
    }

    #pragma unroll
    for (int i = 0; i < 2; i++) {
        int gm = bm + wm * 32 + i * 16;
        #pragma unroll
        for (int j = 0; j < 4; j++)
            wmma::store_matrix_sync(&g_h1[(size_t)gm * C1 + bn + wn * 64 + j * 16],
                                    acc[i][j], C1, wmma::mem_row_major);
    }
}

// ------------------- per-node attention coefficients (layer 1) -------------------
__global__ void alpha1_kernel(const float* __restrict__ asrc, const float* __restrict__ adst) {
    int w = (blockIdx.x * blockDim.x + threadIdx.x) >> 5;
    int lane = threadIdx.x & 31;
    if (w >= N_NODES) return;
    const float* hrow = g_h1 + (size_t)w * C1;
    float s[HEADS] = {0.f, 0.f, 0.f, 0.f};
    float d[HEADS] = {0.f, 0.f, 0.f, 0.f};
    #pragma unroll
    for (int i = 0; i < 8; i++) {
        int col = lane + 32 * i;
        float v = hrow[col];
        int h = i >> 1;
        s[h] += v * __ldg(&asrc[col]);
        d[h] += v * __ldg(&adst[col]);
    }
    #pragma unroll
    for (int h = 0; h < HEADS; h++) {
        #pragma unroll
        for (int o = 16; o > 0; o >>= 1) {
            s[h] += __shfl_xor_sync(0xffffffffu, s[h], o);
            d[h] += __shfl_xor_sync(0xffffffffu, d[h], o);
        }
    }
    if (lane == 0) {
        #pragma unroll
        for (int h = 0; h < HEADS; h++) {
            g_as1[w * HEADS + h] = s[h];
            g_ad1[w * HEADS + h] = d[h];
        }
    }
}

// ------------------- layer 1 aggregation + fused GEMM2 + layer-2 coefficients --------
__global__ void agg1_kernel(const float* __restrict__ b1, const float* __restrict__ W2,
                            const float* __restrict__ a2s, const float* __restrict__ a2d) {
    int node = (blockIdx.x * blockDim.x + threadIdx.x) >> 5;
    int lane = threadIdx.x & 31;
    if (node >= N_NODES) return;
    int beg = g_rowptr[node], end = g_rowptr[node + 1];
    float4 ad = *(const float4*)&g_ad1[node * HEADS];

    float4 mx = make_float4(-1e30f, -1e30f, -1e30f, -1e30f);
    for (int i = beg + lane; i < end; i += 32) {
        int s = g_csrc[i];
        float4 a = *(const float4*)&g_as1[s * HEADS];
        float4 e;
        e.x = lrelu(a.x + ad.x); e.y = lrelu(a.y + ad.y);
        e.z = lrelu(a.z + ad.z); e.w = lrelu(a.w + ad.w);
        g_ee[i] = e;
        mx.x = fmaxf(mx.x, e.x); mx.y = fmaxf(mx.y, e.y);
        mx.z = fmaxf(mx.z, e.z); mx.w = fmaxf(mx.w, e.w);
    }
    #pragma unroll
    for (int o = 16; o > 0; o >>= 1) {
        mx.x = fmaxf(mx.x, __shfl_xor_sync(0xffffffffu, mx.x, o));
        mx.y = fmaxf(mx.y, __shfl_xor_sync(0xffffffffu, mx.y, o));
        mx.z = fmaxf(mx.z, __shfl_xor_sync(0xffffffffu, mx.z, o));
        mx.w = fmaxf(mx.w, __shfl_xor_sync(0xffffffffu, mx.w, o));
    }

    float4 sm = make_float4(0.f, 0.f, 0.f, 0.f);
    for (int i = beg + lane; i < end; i += 32) {
        float4 e = g_ee[i];
        float4 ex;
        ex.x = expf(e.x - mx.x); ex.y = expf(e.y - mx.y);
        ex.z = expf(e.z - mx.z); ex.w = expf(e.w - mx.w);
        g_ee[i] = ex;
        sm.x += ex.x; sm.y += ex.y; sm.z += ex.z; sm.w += ex.w;
    }
    #pragma unroll
    for (int o = 16; o > 0; o >>= 1) {
        sm.x += __shfl_xor_sync(0xffffffffu, sm.x, o);
        sm.y += __shfl_xor_sync(0xffffffffu, sm.y, o);
        sm.z += __shfl_xor_sync(0xffffffffu, sm.z, o);
        sm.w += __shfl_xor_sync(0xffffffffu, sm.w, o);
    }
    float4 inv;
    inv.x = 1.f / sm.x; inv.y = 1.f / sm.y; inv.z = 1.f / sm.z; inv.w = 1.f / sm.w;

    // pass 3: unrolled by 2 for MLP
    float4 acc0 = make_float4(0.f, 0.f, 0.f, 0.f);
    float4 acc1 = make_float4(0.f, 0.f, 0.f, 0.f);
    bool lo = (lane < 16);
    int i = beg;
    for (; i + 1 < end; i += 2) {
        int s0 = g_csrc[i], s1 = g_csrc[i + 1];
        float4 ex0 = __ldg(&g_ee[i]);
        float4 ex1 = __ldg(&g_ee[i + 1]);
        const float4* r0 = (const float4*)(g_h1 + (size_t)s0 * C1);
        const float4* r1 = (const float4*)(g_h1 + (size_t)s1 * C1);
        float4 v00 = r0[lane], v01 = r0[32 + lane];
        float4 v10 = r1[lane], v11 = r1[32 + lane];
        float a00 = (lo ? ex0.x * inv.x : ex0.y * inv.y);
        float a01 = (lo ? ex0.z * inv.z : ex0.w * inv.w);
        float a10 = (lo ? ex1.x * inv.x : ex1.y * inv.y);
        float a11 = (lo ? ex1.z * inv.z : ex1.w * inv.w);
        acc0.x += a00 * v00.x; acc0.y += a00 * v00.y; acc0.z += a00 * v00.z; acc0.w += a00 * v00.w;
        acc1.x += a01 * v01.x; acc1.y += a01 * v01.y; acc1.z += a01 * v01.z; acc1.w += a01 * v01.w;
        acc0.x += a10 * v10.x; acc0.y += a10 * v10.y; acc0.z += a10 * v10.z; acc0.w += a10 * v10.w;
        acc1.x += a11 * v11.x; acc1.y += a11 * v11.y; acc1.z += a11 * v11.z; acc1.w += a11 * v11.w;
    }
    if (i < end) {
        int s = g_csrc[i];
        float4 ex = __ldg(&g_ee[i]);
        const float4* hrow = (const float4*)(g_h1 + (size_t)s * C1);
        float4 v0 = hrow[lane];
        float4 v1 = hrow[32 + lane];
        float a0 = (lo ? ex.x * inv.x : ex.y * inv.y);
        float a1 = (lo ? ex.z * inv.z : ex.w * inv.w);
        acc0.x += a0 * v0.x; acc0.y += a0 * v0.y; acc0.z += a0 * v0.z; acc0.w += a0 * v0.w;
        acc1.x += a1 * v1.x; acc1.y += a1 * v1.y; acc1.z += a1 * v1.z; acc1.w += a1 * v1.w;
    }

    float4 bb0 = __ldg((const float4*)&b1[4 * lane]);
    float4 bb1 = __ldg((const float4*)&b1[128 + 4 * lane]);
    float of[8];
    of[0] = fmaxf(acc0.x + bb0.x, 0.f); of[1] = fmaxf(acc0.y + bb0.y, 0.f);
    of[2] = fmaxf(acc0.z + bb0.z, 0.f); of[3] = fmaxf(acc0.w + bb0.w, 0.f);
    of[4] = fmaxf(acc1.x + bb1.x, 0.f); of[5] = fmaxf(acc1.y + bb1.y, 0.f);
    of[6] = fmaxf(acc1.z + bb1.z, 0.f); of[7] = fmaxf(acc1.w + bb1.w, 0.f);

    // fused GEMM2
    float hacc[CLS] = {};
    const float4* w2v = (const float4*)W2;
    #pragma unroll
    for (int j = 0; j < 8; j++) {
        int k = (j < 4) ? (4 * lane + j) : (128 + 4 * lane + (j - 4));
        float v = of[j];
        float4 wa = __ldg(&w2v[2 * k]);
        float4 wb = __ldg(&w2v[2 * k + 1]);
        hacc[0] += v * wa.x; hacc[1] += v * wa.y; hacc[2] += v * wa.z; hacc[3] += v * wa.w;
        hacc[4] += v * wb.x; hacc[5] += v * wb.y; hacc[6] += v * wb.z; hacc[7] += v * wb.w;
    }
    #pragma unroll
    for (int c = 0; c < CLS; c++)
        #pragma unroll
        for (int o = 16; o > 0; o >>= 1)
            hacc[c] += __shfl_xor_sync(0xffffffffu, hacc[c], o);
    if (lane == 0) {
        float s2 = 0.f, d2 = 0.f;
        #pragma unroll
        for (int c = 0; c < CLS; c++) {
            s2 += hacc[c] * __ldg(&a2s[c]);
            d2 += hacc[c] * __ldg(&a2d[c]);
        }
        float4* h2row = (float4*)(g_h2 + (size_t)node * CLS);
        h2row[0] = make_float4(hacc[0], hacc[1], hacc[2], hacc[3]);
        h2row[1] = make_float4(hacc[4], hacc[5], hacc[6], hacc[7]);
        g_as2[node] = s2;
        g_ad2[node] = d2;
    }
}

// ------------------- layer 2 aggregation + bias + log_softmax -------------------
__global__ void agg2_kernel(const float* __restrict__ b2, float* __restrict__ out) {
    int n = blockIdx.x * blockDim.x + threadIdx.x;
    if (n >= N_NODES) return;
    int beg = g_rowptr[n], end = g_rowptr[n + 1];
    float adv = g_ad2[n];
    float* ebuf = (float*)g_ee;

    float mx = -1e30f;
    for (int i = beg; i < end; i++) {
        float e = lrelu(g_as2[g_csrc[i]] + adv);
        ebuf[i] = e;
        mx = fmaxf(mx, e);
    }
    float sm = 0.f;
    for (int i = beg; i < end; i++) {
        float ex = expf(ebuf[i] - mx);
        ebuf[i] = ex;
        sm += ex;
    }
    float invs = 1.f / sm;
    float acc[CLS] = {};
    for (int i = beg; i < end; i++) {
        int s = g_csrc[i];
        float al = ebuf[i] * invs;
        const float4* hp = (const float4*)(g_h2 + (size_t)s * CLS);
        float4 v0 = hp[0], v1 = hp[1];
        acc[0] += al * v0.x; acc[1] += al * v0.y; acc[2] += al * v0.z; acc[3] += al * v0.w;
        acc[4] += al * v1.x; acc[5] += al * v1.y; acc[6] += al * v1.z; acc[7] += al * v1.w;
    }
    float o[CLS];
    float m2 = -1e30f;
    #pragma unroll
    for (int c = 0; c < CLS; c++) {
        o[c] = acc[c] + __ldg(&b2[c]);
        m2 = fmaxf(m2, o[c]);
    }
    float ls = 0.f;
    #pragma unroll
    for (int c = 0; c < CLS; c++) ls += expf(o[c] - m2);
    ls = logf(ls);
    #pragma unroll
    for (int c = 0; c < CLS; c++) out[(size_t)n * CLS + c] = o[c] - m2 - ls;
}

// ------------------- launcher -------------------
extern "C" void kernel_launch(void* const* d_in, const int* in_sizes, int n_in,
                              void* d_out, int out_size) {
    const float* x    = (const float*)d_in[0];
    const int*   ei   = (const int*)d_in[1];
    const float* W1   = (const float*)d_in[2];
    const float* a1s  = (const float*)d_in[3];
    const float* a1d  = (const float*)d_in[4];
    const float* b1   = (const float*)d_in[5];
    const float* W2   = (const float*)d_in[6];
    const float* a2s  = (const float*)d_in[7];
    const float* a2d  = (const float*)d_in[8];
    const float* b2   = (const float*)d_in[9];
    float* out = (float*)d_out;

    static cudaStream_t s_csr = nullptr, s_tc = nullptr;
    static cudaEvent_t ev_fork = nullptr, ev_csr = nullptr, ev_tc = nullptr;
    if (s_csr == nullptr) {
        cudaStreamCreateWithFlags(&s_csr, cudaStreamNonBlocking);
        cudaStreamCreateWithFlags(&s_tc, cudaStreamNonBlocking);
        cudaEventCreateWithFlags(&ev_fork, cudaEventDisableTiming);
        cudaEventCreateWithFlags(&ev_csr, cudaEventDisableTiming);
        cudaEventCreateWithFlags(&ev_tc, cudaEventDisableTiming);
    }

    // fork
    cudaEventRecord(ev_fork, 0);
    cudaStreamWaitEvent(s_csr, ev_fork, 0);
    cudaStreamWaitEvent(s_tc, ev_fork, 0);

    // side stream 1: CSR build
    zero_counts_kernel<<<(N_NODES + 255) / 256, 256, 0, s_csr>>>();
    hist_kernel<<<(ET + 255) / 256, 256, 0, s_csr>>>(ei);
    scan_a_kernel<<<NPART, 1024, 0, s_csr>>>();
    scan_b_kernel<<<1, 32, 0, s_csr>>>();
    scan_c_kernel<<<NPART, 1024, 0, s_csr>>>();
    scatter_kernel<<<(ET + 255) / 256, 256, 0, s_csr>>>(ei);
    cudaEventRecord(ev_csr, s_csr);

    // side stream 2: tensor-core half of GEMM1 (rows [FF_TILES*128, end))
    gemm1_wmma_kernel<<<dim3(WMMA_TILES, 2), 256, 0, s_tc>>>(x, W1);
    cudaEventRecord(ev_tc, s_tc);

    // main stream: FFMA2 half of GEMM1 (rows [0, FF_TILES*128))
    gemm1_kernel<<<dim3(FF_TILES, 2), 256>>>(x, W1);

    // join tensor half, then alpha1 over all rows
    cudaStreamWaitEvent(0, ev_tc, 0);
    alpha1_kernel<<<(N_NODES * 32 + 255) / 256, 256>>>(a1s, a1d);

    // join CSR, then edge-dependent work
    cudaStreamWaitEvent(0, ev_csr, 0);
    agg1_kernel<<<(N_NODES * 32 + 255) / 256, 256>>>(b1, W2, a2s, a2d);
    agg2_kernel<<<(N_NODES + 255) / 256, 256>>>(b2, out);
}

// round 8
// speedup vs baseline: 1.1271x; 1.1271x over previous
#include <cuda_runtime.h>
#include <math.h>

#define N_NODES 50000
#define N_PAD   50048
#define E_EDGES 800000
#define ET (E_EDGES + N_NODES)   // with self loops
#define F_IN 256
#define C1 256                   // HEADS*HID
#define HEADS 4
#define HID 64
#define CLS 8
#define NEG 0.2f
#define NPART ((N_NODES + 1023) / 1024)   // 49

// ------------------- scratch (device globals; no allocation) -------------------
__device__ float g_h1[(size_t)N_PAD * C1];       // x @ W1
__device__ float g_h2[(size_t)N_NODES * CLS];    // (agg1 out) @ W2
__device__ float g_as1[N_NODES * HEADS];
__device__ float g_ad1[N_NODES * HEADS];
__device__ float g_as2[N_NODES];
__device__ float g_ad2[N_NODES];
__device__ float4 g_ee[ET];                      // per-edge staging; reused by layer2
__device__ int   g_deg[N_NODES];
__device__ int   g_cnt[N_NODES];
__device__ int   g_rowptr[N_NODES + 1];
__device__ int   g_part[NPART];
__device__ int   g_csrc[ET];

__device__ __forceinline__ float lrelu(float x) { return x > 0.f ? x : NEG * x; }

__device__ __forceinline__ unsigned long long dup_f32(float v) {
    unsigned long long r;
    unsigned int u = __float_as_uint(v);
    asm("mov.b64 %0, {%1, %1};" : "=l"(r) : "r"(u));
    return r;
}

// ------------------- CSR build -------------------
__global__ void zero_counts_kernel() {
    int i = blockIdx.x * blockDim.x + threadIdx.x;
    if (i < N_NODES) { g_deg[i] = 0; g_cnt[i] = 0; }
}

__global__ void hist_kernel(const int* __restrict__ ei) {
    int e = blockIdx.x * blockDim.x + threadIdx.x;
    if (e >= ET) return;
    int dst = (e < E_EDGES) ? ei[E_EDGES + e] : (e - E_EDGES);
    atomicAdd(&g_deg[dst], 1);
}

__global__ void scan_a_kernel() {
    __shared__ int warpsums[32];
    int t = threadIdx.x;
    int idx = blockIdx.x * 1024 + t;
    int v = (idx < N_NODES) ? g_deg[idx] : 0;
    int x = v;
    #pragma unroll
    for (int o = 1; o < 32; o <<= 1) {
        int y = __shfl_up_sync(0xffffffffu, x, o);
        if ((t & 31) >= o) x += y;
    }
    if ((t & 31) == 31) warpsums[t >> 5] = x;
    __syncthreads();
    if (t < 32) {
        int y = warpsums[t];
        #pragma unroll
        for (int o = 1; o < 32; o <<= 1) {
            int z = __shfl_up_sync(0xffffffffu, y, o);
            if (t >= o) y += z;
        }
        warpsums[t] = y;
    }
    __syncthreads();
    int incl = x + ((t >= 32) ? warpsums[(t >> 5) - 1] : 0);
    if (idx < N_NODES) g_rowptr[idx] = incl - v;
    if (t == 1023) g_part[blockIdx.x] = incl;
}

__global__ void scan_b_kernel() {
    if (threadIdx.x == 0) {
        int run = 0;
        for (int b = 0; b < NPART; b++) {
            int v = g_part[b];
            g_part[b] = run;
            run += v;
        }
        g_rowptr[N_NODES] = run;
    }
}

__global__ void scan_c_kernel() {
    int idx = blockIdx.x * 1024 + threadIdx.x;
    if (idx < N_NODES) g_rowptr[idx] += g_part[blockIdx.x];
}

__global__ void scatter_kernel(const int* __restrict__ ei) {
    int e = blockIdx.x * blockDim.x + threadIdx.x;
    if (e >= ET) return;
    int src, dst;
    if (e < E_EDGES) { src = ei[e]; dst = ei[E_EDGES + e]; }
    else             { src = e - E_EDGES; dst = src; }
    int pos = g_rowptr[dst] + atomicAdd(&g_cnt[dst], 1);
    g_csrc[pos] = src;
}

// ------------------- GEMM1: g_h1 = x @ W1 via packed fma.rn.f32x2 -------------------
#define BM 128
#define BN 128
#define BK 32

__global__ __launch_bounds__(256, 2) void gemm1_kernel(const float* __restrict__ X,
                                                        const float* __restrict__ W) {
    __shared__ float As[BK][BM + 4];
    __shared__ float Bs[BK][BN];

    int bm = blockIdx.x * BM;
    int bn = blockIdx.y * BN;
    int tid = threadIdx.x;
    int tx = tid & 15;
    int ty = tid >> 4;

    unsigned long long acc[8][4];
    #pragma unroll
    for (int i = 0; i < 8; i++)
        #pragma unroll
        for (int j = 0; j < 4; j++) acc[i][j] = 0ULL;

    for (int k0 = 0; k0 < F_IN; k0 += BK) {
        #pragma unroll
        for (int it = 0; it < 4; it++) {
            int idx = tid + it * 256;
            int m  = idx >> 3, kq = idx & 7;
            int gm = bm + m;
            float4 v = make_float4(0.f, 0.f, 0.f, 0.f);
            if (gm < N_NODES) v = *(const float4*)&X[(size_t)gm * F_IN + k0 + kq * 4];
            As[kq * 4 + 0][m] = v.x;
            As[kq * 4 + 1][m] = v.y;
            As[kq * 4 + 2][m] = v.z;
            As[kq * 4 + 3][m] = v.w;
        }
        #pragma unroll
        for (int it = 0; it < 4; it++) {
            int idx = tid + it * 256;
            int k  = idx >> 5, nq = idx & 31;
            float4 v = *(const float4*)&W[(size_t)(k0 + k) * C1 + bn + nq * 4];
            *(float4*)&Bs[k][nq * 4] = v;
        }
        __syncthreads();

        #pragma unroll 4
        for (int k = 0; k < BK; k++) {
            float4 a0 = *(const float4*)&As[k][ty * 8 + 0];
            float4 a1 = *(const float4*)&As[k][ty * 8 + 4];
            unsigned long long a[8];
            a[0] = dup_f32(a0.x); a[1] = dup_f32(a0.y);
            a[2] = dup_f32(a0.z); a[3] = dup_f32(a0.w);
            a[4] = dup_f32(a1.x); a[5] = dup_f32(a1.y);
            a[6] = dup_f32(a1.z); a[7] = dup_f32(a1.w);
            const unsigned long long* brow = (const unsigned long long*)&Bs[k][0];
            unsigned long long b[4];
            #pragma unroll
            for (int j = 0; j < 4; j++) b[j] = brow[tx + 16 * j];
            #pragma unroll
            for (int i = 0; i < 8; i++)
                #pragma unroll
                for (int j = 0; j < 4; j++)
                    asm("fma.rn.f32x2 %0, %1, %2, %3;"
                        : "=l"(acc[i][j]) : "l"(a[i]), "l"(b[j]), "l"(acc[i][j]));
        }
        __syncthreads();
    }

    #pragma unroll
    for (int i = 0; i < 8; i++) {
        int gm = bm + ty * 8 + i;
        float* orow = &g_h1[(size_t)gm * C1 + bn];
        #pragma unroll
        for (int j = 0; j < 4; j++) {
            int p = tx + 16 * j;
            *(unsigned long long*)&orow[2 * p] = acc[i][j];
        }
    }
}

// ------------------- per-node attention coefficients (layer 1) -------------------
__global__ void alpha1_kernel(const float* __restrict__ asrc, const float* __restrict__ adst) {
    int w = (blockIdx.x * blockDim.x + threadIdx.x) >> 5;
    int lane = threadIdx.x & 31;
    if (w >= N_NODES) return;
    const float* hrow = g_h1 + (size_t)w * C1;
    float s[HEADS] = {0.f, 0.f, 0.f, 0.f};
    float d[HEADS] = {0.f, 0.f, 0.f, 0.f};
    #pragma unroll
    for (int i = 0; i < 8; i++) {
        int col = lane + 32 * i;
        float v = hrow[col];
        int h = i >> 1;
        s[h] += v * __ldg(&asrc[col]);
        d[h] += v * __ldg(&adst[col]);
    }
    #pragma unroll
    for (int h = 0; h < HEADS; h++) {
        #pragma unroll
        for (int o = 16; o > 0; o >>= 1) {
            s[h] += __shfl_xor_sync(0xffffffffu, s[h], o);
            d[h] += __shfl_xor_sync(0xffffffffu, d[h], o);
        }
    }
    if (lane == 0) {
        #pragma unroll
        for (int h = 0; h < HEADS; h++) {
            g_as1[w * HEADS + h] = s[h];
            g_ad1[w * HEADS + h] = d[h];
        }
    }
}

// ------------------- layer 1 aggregation + fused GEMM2 + layer-2 coefficients --------
__global__ void agg1_kernel(const float* __restrict__ b1, const float* __restrict__ W2,
                            const float* __restrict__ a2s, const float* __restrict__ a2d) {
    int node = (blockIdx.x * blockDim.x + threadIdx.x) >> 5;
    int lane = threadIdx.x & 31;
    if (node >= N_NODES) return;
    int beg = g_rowptr[node], end = g_rowptr[node + 1];
    float4 ad = *(const float4*)&g_ad1[node * HEADS];

    // pass 1: gather as1, logits -> g_ee, track max
    float4 mx = make_float4(-1e30f, -1e30f, -1e30f, -1e30f);
    for (int i = beg + lane; i < end; i += 32) {
        int s = g_csrc[i];
        float4 a = *(const float4*)&g_as1[s * HEADS];
        float4 e;
        e.x = lrelu(a.x + ad.x); e.y = lrelu(a.y + ad.y);
        e.z = lrelu(a.z + ad.z); e.w = lrelu(a.w + ad.w);
        g_ee[i] = e;
        mx.x = fmaxf(mx.x, e.x); mx.y = fmaxf(mx.y, e.y);
        mx.z = fmaxf(mx.z, e.z); mx.w = fmaxf(mx.w, e.w);
    }
    #pragma unroll
    for (int o = 16; o > 0; o >>= 1) {
        mx.x = fmaxf(mx.x, __shfl_xor_sync(0xffffffffu, mx.x, o));
        mx.y = fmaxf(mx.y, __shfl_xor_sync(0xffffffffu, mx.y, o));
        mx.z = fmaxf(mx.z, __shfl_xor_sync(0xffffffffu, mx.z, o));
        mx.w = fmaxf(mx.w, __shfl_xor_sync(0xffffffffu, mx.w, o));
    }

    // pass 2: exp, sum, store unnormalized exps
    float4 sm = make_float4(0.f, 0.f, 0.f, 0.f);
    for (int i = beg + lane; i < end; i += 32) {
        float4 e = g_ee[i];
        float4 ex;
        ex.x = expf(e.x - mx.x); ex.y = expf(e.y - mx.y);
        ex.z = expf(e.z - mx.z); ex.w = expf(e.w - mx.w);
        g_ee[i] = ex;
        sm.x += ex.x; sm.y += ex.y; sm.z += ex.z; sm.w += ex.w;
    }
    #pragma unroll
    for (int o = 16; o > 0; o >>= 1) {
        sm.x += __shfl_xor_sync(0xffffffffu, sm.x, o);
        sm.y += __shfl_xor_sync(0xffffffffu, sm.y, o);
        sm.z += __shfl_xor_sync(0xffffffffu, sm.z, o);
        sm.w += __shfl_xor_sync(0xffffffffu, sm.w, o);
    }
    float4 inv;
    inv.x = 1.f / sm.x; inv.y = 1.f / sm.y; inv.z = 1.f / sm.z; inv.w = 1.f / sm.w;

    // pass 3: feature aggregation, unrolled x4 for MLP
    float4 acc0 = make_float4(0.f, 0.f, 0.f, 0.f);
    float4 acc1 = make_float4(0.f, 0.f, 0.f, 0.f);
    bool lo = (lane < 16);
    int i = beg;
    for (; i + 3 < end; i += 4) {
        int s0 = g_csrc[i],     s1 = g_csrc[i + 1];
        int s2 = g_csrc[i + 2], s3 = g_csrc[i + 3];
        float4 ex0 = __ldg(&g_ee[i]);
        float4 ex1 = __ldg(&g_ee[i + 1]);
        float4 ex2 = __ldg(&g_ee[i + 2]);
        float4 ex3 = __ldg(&g_ee[i + 3]);
        const float4* r0 = (const float4*)(g_h1 + (size_t)s0 * C1);
        const float4* r1 = (const float4*)(g_h1 + (size_t)s1 * C1);
        const float4* r2 = (const float4*)(g_h1 + (size_t)s2 * C1);
        const float4* r3 = (const float4*)(g_h1 + (size_t)s3 * C1);
        float4 v00 = r0[lane], v01 = r0[32 + lane];
        float4 v10 = r1[lane], v11 = r1[32 + lane];
        float4 v20 = r2[lane], v21 = r2[32 + lane];
        float4 v30 = r3[lane], v31 = r3[32 + lane];
        float a00 = (lo ? ex0.x * inv.x : ex0.y * inv.y);
        float a01 = (lo ? ex0.z * inv.z : ex0.w * inv.w);
        float a10 = (lo ? ex1.x * inv.x : ex1.y * inv.y);
        float a11 = (lo ? ex1.z * inv.z : ex1.w * inv.w);
        float a20 = (lo ? ex2.x * inv.x : ex2.y * inv.y);
        float a21 = (lo ? ex2.z * inv.z : ex2.w * inv.w);
        float a30 = (lo ? ex3.x * inv.x : ex3.y * inv.y);
        float a31 = (lo ? ex3.z * inv.z : ex3.w * inv.w);
        acc0.x += a00 * v00.x; acc0.y += a00 * v00.y; acc0.z += a00 * v00.z; acc0.w += a00 * v00.w;
        acc1.x += a01 * v01.x; acc1.y += a01 * v01.y; acc1.z += a01 * v01.z; acc1.w += a01 * v01.w;
        acc0.x += a10 * v10.x; acc0.y += a10 * v10.y; acc0.z += a10 * v10.z; acc0.w += a10 * v10.w;
        acc1.x += a11 * v11.x; acc1.y += a11 * v11.y; acc1.z += a11 * v11.z; acc1.w += a11 * v11.w;
        acc0.x += a20 * v20.x; acc0.y += a20 * v20.y; acc0.z += a20 * v20.z; acc0.w += a20 * v20.w;
        acc1.x += a21 * v21.x; acc1.y += a21 * v21.y; acc1.z += a21 * v21.z; acc1.w += a21 * v21.w;
        acc0.x += a30 * v30.x; acc0.y += a30 * v30.y; acc0.z += a30 * v30.z; acc0.w += a30 * v30.w;
        acc1.x += a31 * v31.x; acc1.y += a31 * v31.y; acc1.z += a31 * v31.z; acc1.w += a31 * v31.w;
    }
    for (; i < end; i++) {
        int s = g_csrc[i];
        float4 ex = __ldg(&g_ee[i]);
        const float4* hrow = (const float4*)(g_h1 + (size_t)s * C1);
        float4 v0 = hrow[lane];
        float4 v1 = hrow[32 + lane];
        float a0 = (lo ? ex.x * inv.x : ex.y * inv.y);
        float a1 = (lo ? ex.z * inv.z : ex.w * inv.w);
        acc0.x += a0 * v0.x; acc0.y += a0 * v0.y; acc0.z += a0 * v0.z; acc0.w += a0 * v0.w;
        acc1.x += a1 * v1.x; acc1.y += a1 * v1.y; acc1.z += a1 * v1.z; acc1.w += a1 * v1.w;
    }

    float4 bb0 = __ldg((const float4*)&b1[4 * lane]);
    float4 bb1 = __ldg((const float4*)&b1[128 + 4 * lane]);
    float of[8];
    of[0] = fmaxf(acc0.x + bb0.x, 0.f); of[1] = fmaxf(acc0.y + bb0.y, 0.f);
    of[2] = fmaxf(acc0.z + bb0.z, 0.f); of[3] = fmaxf(acc0.w + bb0.w, 0.f);
    of[4] = fmaxf(acc1.x + bb1.x, 0.f); of[5] = fmaxf(acc1.y + bb1.y, 0.f);
    of[6] = fmaxf(acc1.z + bb1.z, 0.f); of[7] = fmaxf(acc1.w + bb1.w, 0.f);

    // fused GEMM2: h2[c] = sum_k out1[k] * W2[k][c]
    float hacc[CLS] = {};
    const float4* w2v = (const float4*)W2;
    #pragma unroll
    for (int j = 0; j < 8; j++) {
        int k = (j < 4) ? (4 * lane + j) : (128 + 4 * lane + (j - 4));
        float v = of[j];
        float4 wa = __ldg(&w2v[2 * k]);
        float4 wb = __ldg(&w2v[2 * k + 1]);
        hacc[0] += v * wa.x; hacc[1] += v * wa.y; hacc[2] += v * wa.z; hacc[3] += v * wa.w;
        hacc[4] += v * wb.x; hacc[5] += v * wb.y; hacc[6] += v * wb.z; hacc[7] += v * wb.w;
    }
    #pragma unroll
    for (int c = 0; c < CLS; c++)
        #pragma unroll
        for (int o = 16; o > 0; o >>= 1)
            hacc[c] += __shfl_xor_sync(0xffffffffu, hacc[c], o);
    if (lane == 0) {
        float s2 = 0.f, d2 = 0.f;
        #pragma unroll
        for (int c = 0; c < CLS; c++) {
            s2 += hacc[c] * __ldg(&a2s[c]);
            d2 += hacc[c] * __ldg(&a2d[c]);
        }
        float4* h2row = (float4*)(g_h2 + (size_t)node * CLS);
        h2row[0] = make_float4(hacc[0], hacc[1], hacc[2], hacc[3]);
        h2row[1] = make_float4(hacc[4], hacc[5], hacc[6], hacc[7]);
        g_as2[node] = s2;
        g_ad2[node] = d2;
    }
}

// ------------------- layer 2 aggregation + bias + log_softmax -------------------
__global__ void agg2_kernel(const float* __restrict__ b2, float* __restrict__ out) {
    int n = blockIdx.x * blockDim.x + threadIdx.x;
    if (n >= N_NODES) return;
    int beg = g_rowptr[n], end = g_rowptr[n + 1];
    float adv = g_ad2[n];
    float* ebuf = (float*)g_ee;

    float mx = -1e30f;
    for (int i = beg; i < end; i++) {
        float e = lrelu(g_as2[g_csrc[i]] + adv);
        ebuf[i] = e;
        mx = fmaxf(mx, e);
    }
    float sm = 0.f;
    for (int i = beg; i < end; i++) {
        float ex = expf(ebuf[i] - mx);
        ebuf[i] = ex;
        sm += ex;
    }
    float invs = 1.f / sm;
    float acc[CLS] = {};
    for (int i = beg; i < end; i++) {
        int s = g_csrc[i];
        float al = ebuf[i] * invs;
        const float4* hp = (const float4*)(g_h2 + (size_t)s * CLS);
        float4 v0 = hp[0], v1 = hp[1];
        acc[0] += al * v0.x; acc[1] += al * v0.y; acc[2] += al * v0.z; acc[3] += al * v0.w;
        acc[4] += al * v1.x; acc[5] += al * v1.y; acc[6] += al * v1.z; acc[7] += al * v1.w;
    }
    float o[CLS];
    float m2 = -1e30f;
    #pragma unroll
    for (int c = 0; c < CLS; c++) {
        o[c] = acc[c] + __ldg(&b2[c]);
        m2 = fmaxf(m2, o[c]);
    }
    float ls = 0.f;
    #pragma unroll
    for (int c = 0; c < CLS; c++) ls += expf(o[c] - m2);
    ls = logf(ls);
    #pragma unroll
    for (int c = 0; c < CLS; c++) out[(size_t)n * CLS + c] = o[c] - m2 - ls;
}

// ------------------- launcher -------------------
extern "C" void kernel_launch(void* const* d_in, const int* in_sizes, int n_in,
                              void* d_out, int out_size) {
    const float* x    = (const float*)d_in[0];
    const int*   ei   = (const int*)d_in[1];
    const float* W1   = (const float*)d_in[2];
    const float* a1s  = (const float*)d_in[3];
    const float* a1d  = (const float*)d_in[4];
    const float* b1   = (const float*)d_in[5];
    const float* W2   = (const float*)d_in[6];
    const float* a2s  = (const float*)d_in[7];
    const float* a2d  = (const float*)d_in[8];
    const float* b2   = (const float*)d_in[9];
    float* out = (float*)d_out;

    static cudaStream_t s_csr = nullptr;
    static cudaEvent_t ev_fork = nullptr, ev_csr = nullptr;
    if (s_csr == nullptr) {
        cudaStreamCreateWithFlags(&s_csr, cudaStreamNonBlocking);
        cudaEventCreateWithFlags(&ev_fork, cudaEventDisableTiming);
        cudaEventCreateWithFlags(&ev_csr, cudaEventDisableTiming);
    }

    // fork: CSR build on side stream, overlapped with gemm1/alpha1
    cudaEventRecord(ev_fork, 0);
    cudaStreamWaitEvent(s_csr, ev_fork, 0);

    zero_counts_kernel<<<(N_NODES + 255) / 256, 256, 0, s_csr>>>();
    hist_kernel<<<(ET + 255) / 256, 256, 0, s_csr>>>(ei);
    scan_a_kernel<<<NPART, 1024, 0, s_csr>>>();
    scan_b_kernel<<<1, 32, 0, s_csr>>>();
    scan_c_kernel<<<NPART, 1024, 0, s_csr>>>();
    scatter_kernel<<<(ET + 255) / 256, 256, 0, s_csr>>>(ei);
    cudaEventRecord(ev_csr, s_csr);

    // main stream: dense work
    dim3 g1((N_NODES + BM - 1) / BM, C1 / BN);
    gemm1_kernel<<<g1, 256>>>(x, W1);
    alpha1_kernel<<<(N_NODES * 32 + 255) / 256, 256>>>(a1s, a1d);

    // join, then edge-dependent work
    cudaStreamWaitEvent(0, ev_csr, 0);
    agg1_kernel<<<(N_NODES * 32 + 255) / 256, 256>>>(b1, W2, a2s, a2d);
    agg2_kernel<<<(N_NODES + 255) / 256, 256>>>(b2, out);
}